// round 16
// baseline (speedup 1.0000x reference)
#include <cuda_runtime.h>
#include <cuda_bf16.h>

#define NN 100000
#define EE 1600000
#define HH 64

typedef unsigned long long ull;
typedef unsigned int uint;

// Scratch (device globals; no allocation allowed)
__device__ float g_h[NN * HH];
__device__ float g_agg[NN * HH];
__device__ uint  g_wsplit[4 * 8960];   // per "layer": W1h,W1l,W2h,W2l planes, 2240 uints each

__device__ __forceinline__ float frelu(float x) { return x > 0.f ? x : 0.f; }

// ---- bf16 split helpers ----------------------------------------------------
__device__ __forceinline__ void split1(float a, __nv_bfloat16& h, __nv_bfloat16& l) {
    h = __float2bfloat16(a);
    l = __float2bfloat16(a - __bfloat162float(h));
}
__device__ __forceinline__ void split2(float a, float b, uint& hi, uint& lo) {
    __nv_bfloat16 ha, la, hb, lb;
    split1(a, ha, la);
    split1(b, hb, lb);
    hi = (uint)__bfloat16_as_ushort(ha) | ((uint)__bfloat16_as_ushort(hb) << 16);
    lo = (uint)__bfloat16_as_ushort(la) | ((uint)__bfloat16_as_ushort(lb) << 16);
}

// ---- mma.sync m16n8k16 bf16 (fp32 accum) ----------------------------------
__device__ __forceinline__ void mma16816(float* c, const uint* a, uint b0, uint b1) {
    asm volatile(
        "mma.sync.aligned.m16n8k16.row.col.f32.bf16.bf16.f32 "
        "{%0,%1,%2,%3}, {%4,%5,%6,%7}, {%8,%9}, {%0,%1,%2,%3};"
        : "+f"(c[0]), "+f"(c[1]), "+f"(c[2]), "+f"(c[3])
        : "r"(a[0]), "r"(a[1]), "r"(a[2]), "r"(a[3]), "r"(b0), "r"(b1));
}

// ---------------------------------------------------------------------------
// prep_weights: split-2 + transpose all 4 MLPs' weights into global planes.
// layer 0..2 = conv layers; layer 3 = init (rw1 rows 0..63, rw2).
// dest uint [layer*8960 + mat01*4480 + plane*2240 + n*35 + j] holds bf16 pair
// (W[2j][n], W[2j+1][n]) of the hi (plane 0) or lo (plane 1) split.
// ---------------------------------------------------------------------------
__global__ void __launch_bounds__(256) prep_weights(
    const float* __restrict__ cw1, const float* __restrict__ cw2,
    const float* __restrict__ rw1, const float* __restrict__ rw2,
    uint* __restrict__ gw)
{
    int idx = blockIdx.x * 256 + threadIdx.x;
    if (idx >= 4 * 2 * 64 * 32) return;
    int layer = idx >> 12;
    int mat01 = (idx >> 11) & 1;
    int n     = (idx >> 5) & 63;
    int j     = idx & 31;

    const float* W;
    if (layer < 3) W = mat01 ? (cw2 + layer * 4096) : (cw1 + layer * 4096);
    else           W = mat01 ? rw2 : rw1;

    float a = W[(2 * j) * 64 + n];
    float b = W[(2 * j + 1) * 64 + n];
    uint hu, lu;
    split2(a, b, hu, lu);
    int base = layer * 8960 + mat01 * 4480;
    gw[base + n * 35 + j]        = hu;
    gw[base + 2240 + n * 35 + j] = lu;
}

// ---------------------------------------------------------------------------
// Edge kernel (R12, measured best): msg = relu(h[src] + edge_attr);
// agg[dst] += msg. 8 threads/edge, 2 float4 chunks each, exact grid.
// ---------------------------------------------------------------------------
__global__ void __launch_bounds__(256) edge_kernel(
    const float4* __restrict__ h,
    const float4* __restrict__ ea,
    const int* __restrict__ src,
    const int* __restrict__ dst,
    float4* __restrict__ agg)
{
    int t = blockIdx.x * 256 + threadIdx.x;
    int e = t >> 3;
    int c = t & 7;

    int s = __ldg(&src[e]);
    int d = __ldg(&dst[e]);

    float4 a0 = __ldcs(&ea[(size_t)e * 16 + c]);
    float4 a1 = __ldcs(&ea[(size_t)e * 16 + c + 8]);
    float4 h0 = __ldcg(&h[(size_t)s * 16 + c]);
    float4 h1 = __ldcg(&h[(size_t)s * 16 + c + 8]);

    float4 m0, m1;
    m0.x = frelu(a0.x + h0.x); m0.y = frelu(a0.y + h0.y);
    m0.z = frelu(a0.z + h0.z); m0.w = frelu(a0.w + h0.w);
    m1.x = frelu(a1.x + h1.x); m1.y = frelu(a1.y + h1.y);
    m1.z = frelu(a1.z + h1.z); m1.w = frelu(a1.w + h1.w);

    atomicAdd(&agg[(size_t)d * 16 + c], m0);
    atomicAdd(&agg[(size_t)d * 16 + c + 8], m1);
}

// ---------------------------------------------------------------------------
// Tensor-core MLP kernel (conv layers AND init):
//   out = relu_opt(relu(X@W1 + b1 [+ t*rw1_row64])@W2 + b2) [+ resid]
// X source: zidx ? emb[zidx[node]] (init) : in[node] (conv).
// 256 threads = 8 warps, 128 nodes/block, warp owns a 16-node m-tile.
// bf16 split-2: D = Xh*Wh + Xl*Wh + Xh*Wl, fp32 accumulate.
// Weights pre-split by prep_weights and read DIRECTLY via __ldg (L1-resident,
// shared by all blocks) — no weight smem, smem ~38KB -> ~6 blocks/SM.
// ---------------------------------------------------------------------------
#define SX 35
#define OFF_XH  0
#define OFF_XL  (OFF_XH + 128 * SX)       // 4480
#define TC_SMEM_UINTS (OFF_XL + 128 * SX) // 8960
#define TC_SMEM_BYTES (TC_SMEM_UINTS * 4)

__global__ void __launch_bounds__(256) mlp_kernel(
    const float* __restrict__ in,
    const int* __restrict__ zidx,
    const float* __restrict__ emb,
    const float* __restrict__ tvec,
    const float* __restrict__ w64,
    const uint* __restrict__ wsp,       // this layer's 8960-uint split-weight block
    const float* __restrict__ b1, const float* __restrict__ b2,
    const float* __restrict__ resid,
    float* __restrict__ out1, float* __restrict__ out2,
    int relu_out)
{
    extern __shared__ uint su[];
    uint* sXh  = su + OFF_XH;
    uint* sXl  = su + OFF_XL;
    __shared__ float sb1[64], sb2[64], sT[128], sw64[64];
    __shared__ int sZ[128];

    const int tid = threadIdx.x;
    const int base = blockIdx.x * 128;

    if (tid < 64) { sb1[tid] = b1[tid]; sb2[tid] = b2[tid]; }
    if (zidx) {
        if (tid < 128) {
            int nd = base + tid;
            sZ[tid] = (nd < NN) ? zidx[nd] : 0;
            sT[tid] = (nd < NN) ? tvec[nd] : 0.f;
        }
        if (tid >= 128 && tid < 192) sw64[tid - 128] = w64[tid - 128];
        __syncthreads();   // sZ ready before emb gather below
    }

    // ---- stage X: split into hi/lo bf16 pairs -----------------------------
    for (int i = tid; i < 128 * 16; i += 256) {
        int nd = i >> 4, c = i & 15;
        float4 v = make_float4(0.f, 0.f, 0.f, 0.f);
        if (base + nd < NN) {
            if (zidx) v = ((const float4*)emb)[(size_t)sZ[nd] * 16 + c];
            else      v = ((const float4*)in)[(size_t)(base + nd) * 16 + c];
        }
        uint h0, l0, h1, l1;
        split2(v.x, v.y, h0, l0);
        split2(v.z, v.w, h1, l1);
        sXh[nd * SX + 2 * c]     = h0;
        sXh[nd * SX + 2 * c + 1] = h1;
        sXl[nd * SX + 2 * c]     = l0;
        sXl[nd * SX + 2 * c + 1] = l1;
    }
    __syncthreads();

    const uint* gW1h = wsp;
    const uint* gW1l = wsp + 2240;
    const uint* gW2h = wsp + 4480;
    const uint* gW2l = wsp + 6720;

    const int w = tid >> 5, l = tid & 31;
    const int g = l >> 2, tig = l & 3;
    const int wn = w * 16;

    float acc[8][4];

    // ================= GEMM 1: mid = X @ W1 + b1 (+ t-term) ===============
    if (zidx) {
        float t0 = sT[wn + g], t8 = sT[wn + g + 8];
#pragma unroll
        for (int nt = 0; nt < 8; nt++) {
            int c0 = nt * 8 + 2 * tig, c1 = c0 + 1;
            acc[nt][0] = fmaf(t0, sw64[c0], sb1[c0]);
            acc[nt][1] = fmaf(t0, sw64[c1], sb1[c1]);
            acc[nt][2] = fmaf(t8, sw64[c0], sb1[c0]);
            acc[nt][3] = fmaf(t8, sw64[c1], sb1[c1]);
        }
    } else {
#pragma unroll
        for (int nt = 0; nt < 8; nt++) {
            float bA = sb1[nt * 8 + 2 * tig];
            float bB = sb1[nt * 8 + 2 * tig + 1];
            acc[nt][0] = bA; acc[nt][1] = bB; acc[nt][2] = bA; acc[nt][3] = bB;
        }
    }
#pragma unroll
    for (int kt = 0; kt < 4; kt++) {
        uint ah[4], al[4];
        int r0 = (wn + g) * SX + kt * 8 + tig;
        int r1 = (wn + g + 8) * SX + kt * 8 + tig;
        ah[0] = sXh[r0]; ah[1] = sXh[r1]; ah[2] = sXh[r0 + 4]; ah[3] = sXh[r1 + 4];
        al[0] = sXl[r0]; al[1] = sXl[r1]; al[2] = sXl[r0 + 4]; al[3] = sXl[r1 + 4];
#pragma unroll
        for (int nt = 0; nt < 8; nt++) {
            int bo = (nt * 8 + g) * SX + kt * 8 + tig;
            uint bh0 = __ldg(&gW1h[bo]), bh1 = __ldg(&gW1h[bo + 4]);
            uint bl0 = __ldg(&gW1l[bo]), bl1 = __ldg(&gW1l[bo + 4]);
            mma16816(acc[nt], ah, bh0, bh1);
            mma16816(acc[nt], al, bh0, bh1);
            mma16816(acc[nt], ah, bl0, bl1);
        }
    }

    // ---- mid: relu, re-split into warp-private rows -----------------------
    __syncwarp();
#pragma unroll
    for (int nt = 0; nt < 8; nt++) {
        float v0 = frelu(acc[nt][0]), v1 = frelu(acc[nt][1]);
        float v2 = frelu(acc[nt][2]), v3 = frelu(acc[nt][3]);
        uint h0, l0, h2, l2;
        split2(v0, v1, h0, l0);
        split2(v2, v3, h2, l2);
        sXh[(wn + g) * SX + nt * 4 + tig]     = h0;
        sXl[(wn + g) * SX + nt * 4 + tig]     = l0;
        sXh[(wn + g + 8) * SX + nt * 4 + tig] = h2;
        sXl[(wn + g + 8) * SX + nt * 4 + tig] = l2;
    }
    __syncwarp();

    // ================= GEMM 2: out = mid @ W2 + b2 =======================
#pragma unroll
    for (int nt = 0; nt < 8; nt++) {
        float bA = sb2[nt * 8 + 2 * tig];
        float bB = sb2[nt * 8 + 2 * tig + 1];
        acc[nt][0] = bA; acc[nt][1] = bB; acc[nt][2] = bA; acc[nt][3] = bB;
    }
#pragma unroll
    for (int kt = 0; kt < 4; kt++) {
        uint ah[4], al[4];
        int r0 = (wn + g) * SX + kt * 8 + tig;
        int r1 = (wn + g + 8) * SX + kt * 8 + tig;
        ah[0] = sXh[r0]; ah[1] = sXh[r1]; ah[2] = sXh[r0 + 4]; ah[3] = sXh[r1 + 4];
        al[0] = sXl[r0]; al[1] = sXl[r1]; al[2] = sXl[r0 + 4]; al[3] = sXl[r1 + 4];
#pragma unroll
        for (int nt = 0; nt < 8; nt++) {
            int bo = (nt * 8 + g) * SX + kt * 8 + tig;
            uint bh0 = __ldg(&gW2h[bo]), bh1 = __ldg(&gW2h[bo + 4]);
            uint bl0 = __ldg(&gW2l[bo]), bl1 = __ldg(&gW2l[bo + 4]);
            mma16816(acc[nt], ah, bh0, bh1);
            mma16816(acc[nt], al, bh0, bh1);
            mma16816(acc[nt], ah, bl0, bl1);
        }
    }

    // ---- epilogue: optional relu, optional resid, store -------------------
    const int n0 = base + wn + g;
    const int n1 = n0 + 8;
#pragma unroll
    for (int nt = 0; nt < 8; nt++) {
        int col = nt * 8 + 2 * tig;
        if (n0 < NN) {
            float v0 = acc[nt][0], v1 = acc[nt][1];
            if (relu_out) { v0 = frelu(v0); v1 = frelu(v1); }
            if (resid) {
                float2 r = *(const float2*)&resid[(size_t)n0 * 64 + col];
                v0 += r.x; v1 += r.y;
            }
            float2 o = make_float2(v0, v1);
            *(float2*)&out1[(size_t)n0 * 64 + col] = o;
            if (out2) *(float2*)&out2[(size_t)n0 * 64 + col] = o;
        }
        if (n1 < NN) {
            float v2 = acc[nt][2], v3 = acc[nt][3];
            if (relu_out) { v2 = frelu(v2); v3 = frelu(v3); }
            if (resid) {
                float2 r = *(const float2*)&resid[(size_t)n1 * 64 + col];
                v2 += r.x; v3 += r.y;
            }
            float2 o = make_float2(v2, v3);
            *(float2*)&out1[(size_t)n1 * 64 + col] = o;
            if (out2) *(float2*)&out2[(size_t)n1 * 64 + col] = o;
        }
    }
}

// ---------------------------------------------------------------------------
// Launch
// ---------------------------------------------------------------------------
extern "C" void kernel_launch(void* const* d_in, const int* in_sizes, int n_in,
                              void* d_out, int out_size)
{
    const int*   z    = (const int*)  d_in[0];
    const int*   ei   = (const int*)  d_in[1];   // [2, E]: src = ei, dst = ei + EE
    const float* ea   = (const float*)d_in[2];
    const float* t    = (const float*)d_in[3];
    const float* emb  = (const float*)d_in[4];
    const float* rw1  = (const float*)d_in[5];
    const float* rb1  = (const float*)d_in[6];
    const float* rw2  = (const float*)d_in[7];
    const float* rb2  = (const float*)d_in[8];
    const float* cw1  = (const float*)d_in[9];
    const float* cb1  = (const float*)d_in[10];
    const float* cw2  = (const float*)d_in[11];
    const float* cb2  = (const float*)d_in[12];
    float* out = (float*)d_out;

    float* hp = nullptr;
    float* ap = nullptr;
    uint*  gw = nullptr;
    cudaGetSymbolAddress((void**)&hp, g_h);
    cudaGetSymbolAddress((void**)&ap, g_agg);
    cudaGetSymbolAddress((void**)&gw, g_wsplit);

    cudaFuncSetAttribute(mlp_kernel, cudaFuncAttributeMaxDynamicSharedMemorySize, TC_SMEM_BYTES);

    const int nblk_mlp  = (NN + 127) / 128;
    const int nblk_edge = (EE * 8) / 256;   // 50000 exact

    // one-time per launch: split/transpose all weights
    prep_weights<<<64, 256>>>(cw1, cw2, rw1, rw2, gw);

    // init: TC path, X = emb[z], + t-term; writes g_h and g_agg
    mlp_kernel<<<nblk_mlp, 256, TC_SMEM_BYTES>>>(
        nullptr, z, emb, t, rw1 + 64 * 64, gw + 3 * 8960,
        rb1, rb2, nullptr, hp, ap, 0);

    for (int li = 0; li < 3; li++) {
        edge_kernel<<<nblk_edge, 256>>>((const float4*)hp, (const float4*)ea,
                                        ei, ei + EE, (float4*)ap);
        const float* b1 = cb1 + li * 64;
        const float* b2 = cb2 + li * 64;
        const uint*  wl = gw + li * 8960;
        if (li < 2) {
            mlp_kernel<<<nblk_mlp, 256, TC_SMEM_BYTES>>>(
                ap, nullptr, nullptr, nullptr, nullptr, wl, b1, b2, hp, hp, ap, 1);
        } else {
            mlp_kernel<<<nblk_mlp, 256, TC_SMEM_BYTES>>>(
                ap, nullptr, nullptr, nullptr, nullptr, wl, b1, b2, hp, out, nullptr, 0);
        }
    }
}